// round 9
// baseline (speedup 1.0000x reference)
#include <cuda_runtime.h>
#include <cstdint>

#define N_PARTICLES 131072
#define N_BEAMS     90
#define MAP_HW      800
#define N_TOTAL     (N_PARTICLES * N_BEAMS)
#define MAX_RANGE_PX 150.0f
#define OCC_THR     0.35f
#define BATCH       8

// fp32(pi/180), identical to jnp.deg2rad's fp32 constant
#define DEG2RAD 0.017453292519943295f
// XLA algebraic simplifier rewrites x/10 -> x * fp32(0.1)
#define INV10 0.1f

// Per-particle precomputed state: {x_laser, y_laser, yaw, unused}
__device__ float4 g_part[N_PARTICLES];

// ---------------------------------------------------------------------------
// Kernel 1: per-particle prologue (1/90th of the threads).
// Bit-identical to the eager-JAX prologue: separate mul/add roundings,
// reciprocal-multiply for /10, libdevice cosf/sinf.
// ---------------------------------------------------------------------------
__global__ void __launch_bounds__(256)
particle_prep_kernel(const float* __restrict__ X)   // [N_PARTICLES, 3]
{
    int p = blockIdx.x * blockDim.x + threadIdx.x;
    if (p >= N_PARTICLES) return;

    float xb  = X[p * 3 + 0];
    float yb  = X[p * 3 + 1];
    float yaw = X[p * 3 + 2];

    float cy = cosf(yaw);
    float sy = sinf(yaw);

    float xl = __fmul_rn(__fadd_rn(xb, __fmul_rn(25.0f, cy)), INV10);
    float yl = __fmul_rn(__fadd_rn(yb, __fmul_rn(25.0f, sy)), INV10);

    g_part[p] = make_float4(xl, yl, yaw, 0.0f);
}

// ---------------------------------------------------------------------------
// Kernel 2: one thread per (particle, beam) ray, marched in batches of 8
// independent loads (MLP=8) instead of a serial load->test chain.
// ---------------------------------------------------------------------------
__global__ void __launch_bounds__(256)
raycast_kernel(const float* __restrict__ occ_map,   // [800, 800]
               float* __restrict__ out)             // [N_PARTICLES, 90]
{
    int idx = blockIdx.x * blockDim.x + threadIdx.x;
    if (idx >= N_TOTAL) return;

    int p = idx / N_BEAMS;          // magic-multiply, no real division
    int b = idx - p * N_BEAMS;

    // One LDG.128, broadcast across the 90 threads of this particle.
    float4 s = g_part[p];
    float xl  = s.x;
    float yl  = s.y;
    float yaw = s.z;

    // ang = fp32(deg * pi/180) + yaw : two separate eager-op roundings
    float ang_deg = (float)(-90 + 2 * b);
    float ang = __fadd_rn(__fmul_rn(ang_deg, DEG2RAD), yaw);
    float ca = cosf(ang);
    float sa = sinf(ang);

    // Batched march. Values loaded are bit-identical to the serial version;
    // the reverse scan selects the SMALLEST hitting r, so first-hit semantics
    // (== reference's min over steps) are preserved exactly. Steps r > 150
    // are masked to occ=0 (never hit).
    float hit = MAX_RANGE_PX;
    for (int base = 0; base <= 150; base += BATCH) {
        float occ[BATCH];
        #pragma unroll
        for (int j = 0; j < BATCH; j++) {
            int r = base + j;
            float rf = (float)r;
            // fma.rn contraction matches the fused XLA scan body
            float xp = __fmaf_rn(ca, rf, xl);
            float yp = __fmaf_rn(sa, rf, yl);
            // round-half-even to int (== jnp.round + astype for our bounded,
            // non-NaN range), clamp in integer domain (== clip to [0,799]).
            int xi = min(max(__float2int_rn(xp), 0), MAP_HW - 1);
            int yi = min(max(__float2int_rn(yp), 0), MAP_HW - 1);
            occ[j] = (r <= 150) ? __ldg(&occ_map[yi * MAP_HW + xi]) : 0.0f;
        }
        // Reverse overwrite -> smallest hitting r in this batch.
        int hitstep = -1;
        #pragma unroll
        for (int j = BATCH - 1; j >= 0; j--)
            if (occ[j] > OCC_THR) hitstep = base + j;
        if (hitstep >= 0) { hit = (float)hitstep; break; }
    }

    out[idx] = hit;
}

extern "C" void kernel_launch(void* const* d_in, const int* in_sizes, int n_in,
                              void* d_out, int out_size)
{
    const float* X       = (const float*)d_in[0];   // X_t1 [131072, 3]
    const float* occ_map = (const float*)d_in[1];   // occupancy_map [800, 800]
    float* out           = (float*)d_out;           // [131072, 90]

    const int threads = 256;

    particle_prep_kernel<<<(N_PARTICLES + threads - 1) / threads, threads>>>(X);

    raycast_kernel<<<(N_TOTAL + threads - 1) / threads, threads>>>(occ_map, out);
}

// round 10
// speedup vs baseline: 1.6299x; 1.6299x over previous
#include <cuda_runtime.h>
#include <cstdint>

#define N_PARTICLES 131072
#define N_BEAMS     90
#define MAP_HW      800
#define N_TOTAL     (N_PARTICLES * N_BEAMS)
#define MAX_RANGE_PX 150.0f
#define OCC_THR     0.35f

// fp32(pi/180), identical to jnp.deg2rad's fp32 constant
#define DEG2RAD 0.017453292519943295f
// XLA algebraic simplifier rewrites x/10 -> x * fp32(0.1)
#define INV10 0.1f

// Per-particle precomputed state: {x_laser, y_laser, yaw, unused}
__device__ float4 g_part[N_PARTICLES];

// ---------------------------------------------------------------------------
// Kernel 1: per-particle prologue (1/90th of the threads).
// Bit-identical to the eager-JAX prologue: separate mul/add roundings,
// reciprocal-multiply for /10. sincosf proven bit-identical to sinf/cosf
// (R3==R4==R6 rel_err evidence across 11.8M evaluations).
// ---------------------------------------------------------------------------
__global__ void __launch_bounds__(256)
particle_prep_kernel(const float* __restrict__ X)   // [N_PARTICLES, 3]
{
    int p = blockIdx.x * blockDim.x + threadIdx.x;
    if (p >= N_PARTICLES) return;

    float xb  = X[p * 3 + 0];
    float yb  = X[p * 3 + 1];
    float yaw = X[p * 3 + 2];

    float sy, cy;
    sincosf(yaw, &sy, &cy);

    float xl = __fmul_rn(__fadd_rn(xb, __fmul_rn(25.0f, cy)), INV10);
    float yl = __fmul_rn(__fadd_rn(yb, __fmul_rn(25.0f, sy)), INV10);

    g_part[p] = make_float4(xl, yl, yaw, 0.0f);
}

// ---------------------------------------------------------------------------
// Kernel 2: one thread per (particle, beam) ray. Serial early-exit march
// (R8 structure — issue-bound, so minimum instructions wins).
// ---------------------------------------------------------------------------
__global__ void __launch_bounds__(256)
raycast_kernel(const float* __restrict__ occ_map,   // [800, 800]
               float* __restrict__ out)             // [N_PARTICLES, 90]
{
    int idx = blockIdx.x * blockDim.x + threadIdx.x;
    if (idx >= N_TOTAL) return;

    int p = idx / N_BEAMS;          // magic-multiply, no real division
    int b = idx - p * N_BEAMS;

    // One LDG.128, broadcast across the 90 threads of this particle.
    float4 s = g_part[p];
    float xl  = s.x;
    float yl  = s.y;
    float yaw = s.z;

    // ang = fp32(deg * pi/180) + yaw : two separate eager-op roundings.
    // One sincosf (shared range reduction) instead of cosf+sinf.
    float ang_deg = (float)(-90 + 2 * b);
    float ang = __fadd_rn(__fmul_rn(ang_deg, DEG2RAD), yaw);
    float sa, ca;
    sincosf(ang, &sa, &ca);

    // Serial march with early exit (== reference's min over steps).
    // rf kept as an exact fp32 counter (integers <= 150, FADD is exact),
    // dropping the per-step I2F.
    float hit = MAX_RANGE_PX;
    float rf = 0.0f;
    for (int r = 0; r <= 150; r++, rf += 1.0f) {
        // fma.rn contraction matches the fused XLA scan body
        float xp = __fmaf_rn(ca, rf, xl);
        float yp = __fmaf_rn(sa, rf, yl);
        // round-half-even to int (== jnp.round + astype for bounded, non-NaN
        // range), clamp in integer domain (== clip to [0,799]).
        int xi = min(max(__float2int_rn(xp), 0), MAP_HW - 1);
        int yi = min(max(__float2int_rn(yp), 0), MAP_HW - 1);
        float occ = __ldg(&occ_map[yi * MAP_HW + xi]);
        if (occ > OCC_THR) { hit = rf; break; }
    }

    out[idx] = hit;
}

extern "C" void kernel_launch(void* const* d_in, const int* in_sizes, int n_in,
                              void* d_out, int out_size)
{
    const float* X       = (const float*)d_in[0];   // X_t1 [131072, 3]
    const float* occ_map = (const float*)d_in[1];   // occupancy_map [800, 800]
    float* out           = (float*)d_out;           // [131072, 90]

    const int threads = 256;

    particle_prep_kernel<<<(N_PARTICLES + threads - 1) / threads, threads>>>(X);

    raycast_kernel<<<(N_TOTAL + threads - 1) / threads, threads>>>(occ_map, out);
}

// round 12
// speedup vs baseline: 1.8921x; 1.1608x over previous
#include <cuda_runtime.h>
#include <cstdint>

#define N_PARTICLES 131072
#define N_BEAMS     90
#define MAP_HW      800
#define MAX_RANGE_PX 150.0f
#define OCC_THR     0.35f

#define THREADS_PER_PART (N_BEAMS / 2)               // 45: 2 rays per thread
#define N_THREADS   (N_PARTICLES * THREADS_PER_PART)

// fp32(pi/180), identical to jnp.deg2rad's fp32 constant
#define DEG2RAD 0.017453292519943295f
// XLA algebraic simplifier rewrites x/10 -> x * fp32(0.1)
#define INV10 0.1f

// Per-particle precomputed state: {x_laser, y_laser, yaw, unused}
__device__ float4 g_part[N_PARTICLES];

// ---------------------------------------------------------------------------
// Kernel 1: per-particle prologue. Bit-identical to the eager-JAX prologue:
// separate mul/add roundings, reciprocal-multiply for /10, libdevice trig.
// ---------------------------------------------------------------------------
__global__ void __launch_bounds__(256)
particle_prep_kernel(const float* __restrict__ X)   // [N_PARTICLES, 3]
{
    int p = blockIdx.x * blockDim.x + threadIdx.x;
    if (p >= N_PARTICLES) return;

    float xb  = X[p * 3 + 0];
    float yb  = X[p * 3 + 1];
    float yaw = X[p * 3 + 2];

    float sy, cy;
    sincosf(yaw, &sy, &cy);

    float xl = __fmul_rn(__fadd_rn(xb, __fmul_rn(25.0f, cy)), INV10);
    float yl = __fmul_rn(__fadd_rn(yb, __fmul_rn(25.0f, sy)), INV10);

    g_part[p] = make_float4(xl, yl, yaw, 0.0f);
}

// ---------------------------------------------------------------------------
// Kernel 2: TWO rays per thread (beams 2t, 2t+1). Two independent sincosf
// chains (ILP=2 on the dominant latency chain) and a fused branchless march
// with MLP=2 on the map loads.
// ---------------------------------------------------------------------------
__global__ void __launch_bounds__(256)
raycast_kernel(const float* __restrict__ occ_map,   // [800, 800]
               float* __restrict__ out)             // [N_PARTICLES, 90]
{
    int idx = blockIdx.x * blockDim.x + threadIdx.x;
    if (idx >= N_THREADS) return;

    int p = idx / THREADS_PER_PART;                 // magic-multiply
    int t = idx - p * THREADS_PER_PART;

    // One LDG.128, broadcast across the 45 threads of this particle.
    float4 s = g_part[p];
    float xl  = s.x;
    float yl  = s.y;
    float yaw = s.z;

    // Beam angles for 2t and 2t+1: deg = -90 + 2*b
    float deg0 = (float)(-90 + 4 * t);
    float deg1 = (float)(-88 + 4 * t);
    float ang0 = __fadd_rn(__fmul_rn(deg0, DEG2RAD), yaw);
    float ang1 = __fadd_rn(__fmul_rn(deg1, DEG2RAD), yaw);

    // Two independent polynomial chains -> compiler interleaves (ILP=2).
    float sa0, ca0, sa1, ca1;
    sincosf(ang0, &sa0, &ca0);
    sincosf(ang1, &sa1, &ca1);

    // Fused march, branchless min-update (exactly the reference's
    // min-over-steps semantics; loads past the hit are value-discarded).
    float hit0 = MAX_RANGE_PX;
    float hit1 = MAX_RANGE_PX;
    float rf = 0.0f;
    #pragma unroll 1
    for (int r = 0; r <= 150; r++, rf += 1.0f) {
        // ray 0
        float xp0 = __fmaf_rn(ca0, rf, xl);
        float yp0 = __fmaf_rn(sa0, rf, yl);
        int xi0 = min(max(__float2int_rn(xp0), 0), MAP_HW - 1);
        int yi0 = min(max(__float2int_rn(yp0), 0), MAP_HW - 1);
        // ray 1
        float xp1 = __fmaf_rn(ca1, rf, xl);
        float yp1 = __fmaf_rn(sa1, rf, yl);
        int xi1 = min(max(__float2int_rn(xp1), 0), MAP_HW - 1);
        int yi1 = min(max(__float2int_rn(yp1), 0), MAP_HW - 1);

        float occ0 = __ldg(&occ_map[yi0 * MAP_HW + xi0]);
        float occ1 = __ldg(&occ_map[yi1 * MAP_HW + xi1]);

        hit0 = fminf(hit0, (occ0 > OCC_THR) ? rf : MAX_RANGE_PX);
        hit1 = fminf(hit1, (occ1 > OCC_THR) ? rf : MAX_RANGE_PX);

        // exit once BOTH rays have hit
        if (fmaxf(hit0, hit1) < MAX_RANGE_PX) break;
    }

    // Adjacent beams -> one aligned 8-byte store (offset 2t is even).
    reinterpret_cast<float2*>(out + (size_t)p * N_BEAMS)[t] =
        make_float2(hit0, hit1);
}

extern "C" void kernel_launch(void* const* d_in, const int* in_sizes, int n_in,
                              void* d_out, int out_size)
{
    const float* X       = (const float*)d_in[0];   // X_t1 [131072, 3]
    const float* occ_map = (const float*)d_in[1];   // occupancy_map [800, 800]
    float* out           = (float*)d_out;           // [131072, 90]

    const int threads = 256;

    particle_prep_kernel<<<(N_PARTICLES + threads - 1) / threads, threads>>>(X);

    raycast_kernel<<<(N_THREADS + threads - 1) / threads, threads>>>(occ_map, out);
}

// round 17
// speedup vs baseline: 2.7149x; 1.4349x over previous
#include <cuda_runtime.h>
#include <cstdint>

#define N_PARTICLES 131072
#define N_BEAMS     90
#define MAP_HW      800
#define MAX_RANGE_PX 150.0f
#define OCC_THR     0.35f

// fp32(pi/180), identical to jnp.deg2rad's fp32 constant
#define DEG2RAD 0.017453292519943295f
// XLA algebraic simplifier rewrites x/10 -> x * fp32(0.1)
#define INV10 0.1f

// Per-particle precomputed state: {x_laser, y_laser, yaw, hit-at-r0 flag}
__device__ float4 g_part[N_PARTICLES];

// ---------------------------------------------------------------------------
// Kernel 1: per-particle prologue. Bit-identical to the eager-JAX prologue
// (separate mul/add roundings, reciprocal-multiply for /10, libdevice trig),
// plus the r=0 occupancy test: every beam's r=0 pixel is (rint(xl),rint(yl)),
// so occ0 > thr  =>  the particle's whole output row is exactly 0.
// ---------------------------------------------------------------------------
__global__ void __launch_bounds__(256)
particle_prep_kernel(const float* __restrict__ X,     // [N_PARTICLES, 3]
                     const float* __restrict__ occ_map)
{
    int p = blockIdx.x * blockDim.x + threadIdx.x;    // exact grid, no check

    float xb  = X[p * 3 + 0];
    float yb  = X[p * 3 + 1];
    float yaw = X[p * 3 + 2];

    float sy, cy;
    sincosf(yaw, &sy, &cy);

    float xl = __fmul_rn(__fadd_rn(xb, __fmul_rn(25.0f, cy)), INV10);
    float yl = __fmul_rn(__fadd_rn(yb, __fmul_rn(25.0f, sy)), INV10);

    // r=0 pixel: xp = fma(ca, 0, xl) == xl exactly, for every beam.
    int xi = min(max(__float2int_rn(xl), 0), MAP_HW - 1);
    int yi = min(max(__float2int_rn(yl), 0), MAP_HW - 1);
    float occ0 = __ldg(&occ_map[yi * MAP_HW + xi]);

    g_part[p] = make_float4(xl, yl, yaw, (occ0 > OCC_THR) ? 1.0f : 0.0f);
}

// ---------------------------------------------------------------------------
// Kernel 2: ONE WARP PER PARTICLE, 3 rays per lane (96 slots for 90 beams;
// lanes 30,31 carry dummies with hit preset to 0). Warp-uniform r0-flag skip
// covers 65% of particles with ~12 instructions.
// ---------------------------------------------------------------------------
__global__ void __launch_bounds__(256)
raycast_kernel(const float* __restrict__ occ_map,   // [800, 800]
               float* __restrict__ out)             // [N_PARTICLES, 90]
{
    int tid  = blockIdx.x * blockDim.x + threadIdx.x;
    int p    = tid >> 5;                            // particle == warp id
    int lane = tid & 31;

    float4 s = g_part[p];                           // broadcast across warp
    float* orow = out + (size_t)p * N_BEAMS;

    int  b0    = 3 * lane;                          // beams b0, b0+1, b0+2
    bool valid = (b0 < N_BEAMS);                    // lanes 30,31: dummy

    if (s.w != 0.0f) {                              // warp-uniform fast path
        if (valid) {
            orow[b0 + 0] = 0.0f;
            orow[b0 + 1] = 0.0f;
            orow[b0 + 2] = 0.0f;
        }
        return;
    }

    float xl  = s.x;
    float yl  = s.y;
    float yaw = s.z;

    // ang = fp32(deg * pi/180) + yaw : two separate eager-op roundings.
    float deg0 = (float)(-90 + 6 * lane);
    float ang0 = __fadd_rn(__fmul_rn(deg0,        DEG2RAD), yaw);
    float ang1 = __fadd_rn(__fmul_rn(deg0 + 2.0f, DEG2RAD), yaw);
    float ang2 = __fadd_rn(__fmul_rn(deg0 + 4.0f, DEG2RAD), yaw);

    // Three independent trig chains (ILP=3).
    float sa0, ca0, sa1, ca1, sa2, ca2;
    sincosf(ang0, &sa0, &ca0);
    sincosf(ang1, &sa1, &ca1);
    sincosf(ang2, &sa2, &ca2);

    // March r=1..149:
    //  - r=0 is the (false) flag => known miss, skip exactly.
    //  - r=150 contributes min(hit,150) whether hit or miss => always 150,
    //    already the init value => skip exactly.
    // Branchless min-update == reference's min-over-steps semantics.
    float h0 = valid ? MAX_RANGE_PX : 0.0f;
    float h1 = valid ? MAX_RANGE_PX : 0.0f;
    float h2 = valid ? MAX_RANGE_PX : 0.0f;
    float rf = 1.0f;
    #pragma unroll 1
    for (int r = 1; r < 150; r++, rf += 1.0f) {
        float xp0 = __fmaf_rn(ca0, rf, xl), yp0 = __fmaf_rn(sa0, rf, yl);
        float xp1 = __fmaf_rn(ca1, rf, xl), yp1 = __fmaf_rn(sa1, rf, yl);
        float xp2 = __fmaf_rn(ca2, rf, xl), yp2 = __fmaf_rn(sa2, rf, yl);

        int xi0 = min(max(__float2int_rn(xp0), 0), MAP_HW - 1);
        int yi0 = min(max(__float2int_rn(yp0), 0), MAP_HW - 1);
        int xi1 = min(max(__float2int_rn(xp1), 0), MAP_HW - 1);
        int yi1 = min(max(__float2int_rn(yp1), 0), MAP_HW - 1);
        int xi2 = min(max(__float2int_rn(xp2), 0), MAP_HW - 1);
        int yi2 = min(max(__float2int_rn(yp2), 0), MAP_HW - 1);

        float occ0 = __ldg(&occ_map[yi0 * MAP_HW + xi0]);
        float occ1 = __ldg(&occ_map[yi1 * MAP_HW + xi1]);
        float occ2 = __ldg(&occ_map[yi2 * MAP_HW + xi2]);

        h0 = fminf(h0, (occ0 > OCC_THR) ? rf : MAX_RANGE_PX);
        h1 = fminf(h1, (occ1 > OCC_THR) ? rf : MAX_RANGE_PX);
        h2 = fminf(h2, (occ2 > OCC_THR) ? rf : MAX_RANGE_PX);

        if (fmaxf(h0, fmaxf(h1, h2)) < MAX_RANGE_PX) break;
    }

    if (valid) {
        orow[b0 + 0] = h0;
        orow[b0 + 1] = h1;
        orow[b0 + 2] = h2;
    }
}

extern "C" void kernel_launch(void* const* d_in, const int* in_sizes, int n_in,
                              void* d_out, int out_size)
{
    const float* X       = (const float*)d_in[0];   // X_t1 [131072, 3]
    const float* occ_map = (const float*)d_in[1];   // occupancy_map [800, 800]
    float* out           = (float*)d_out;           // [131072, 90]

    const int threads = 256;

    // 131072 / 256 = 512 blocks, exact
    particle_prep_kernel<<<N_PARTICLES / threads, threads>>>(X, occ_map);

    // one warp per particle: 131072 * 32 / 256 = 16384 blocks, exact
    raycast_kernel<<<(N_PARTICLES * 32) / threads, threads>>>(occ_map, out);
}